// round 2
// baseline (speedup 1.0000x reference)
#include <cuda_runtime.h>
#include <cuda_bf16.h>
#include <math.h>

#define MAXN 50000
#define MAXE 800000
#define EPS 1e-5f
#define NEG_SLOPE 0.2f

// ---------------- scratch (device globals; no allocation allowed) ----------------
__device__ __align__(16) float g_P  [(size_t)MAXN * 128];   // h = x @ W^T
__device__ __align__(16) float g_ACC[(size_t)MAXN * 128];   // aggregation accumulator
__device__ __align__(16) float g_IN [(size_t)MAXN * 128];   // layer input (BN output)
__device__ float    g_as [MAXN];
__device__ float    g_ad [MAXN];
__device__ unsigned g_mkey[MAXN];                // encoded segment max
__device__ float    g_s  [MAXN];                 // segment softmax denominator
__device__ float    g_e  [MAXE + MAXN];          // per-edge scratch (e, then exp)
__device__ int      g_src[MAXE];
__device__ int      g_dst[MAXE];
__device__ float    g_cs [128];                  // column sums (BN)
__device__ float    g_cq [128];                  // column sumsq (BN)
__device__ int      g_is64;                      // edge_index dtype flag

// order-preserving float<->uint encoding for atomicMax over signed floats
__device__ __forceinline__ unsigned fenc(float f) {
    unsigned u = __float_as_uint(f);
    return (u & 0x80000000u) ? ~u : (u | 0x80000000u);
}
__device__ __forceinline__ float fdec(unsigned u) {
    return (u & 0x80000000u) ? __uint_as_float(u ^ 0x80000000u)
                             : __uint_as_float(~u);
}

// ---------------- kernels ----------------

// Detect whether edge_index is int64 or int32. For int64 values < 2^31 the
// high (odd, little-endian) 32-bit words are all zero; for int32 random
// indices in [0, 50000) the chance 64 consecutive odd words are all zero
// is ~ (1/50000)^64.
__global__ void k_detect(const int* __restrict__ w) {
    if (threadIdx.x == 0 && blockIdx.x == 0) {
        int all_zero = 1;
        for (int i = 0; i < 64; i++)
            if (w[2 * i + 1] != 0) { all_zero = 0; break; }
        g_is64 = all_zero;
    }
}

__global__ void k_convert(const void* __restrict__ ei, int E) {
    int i = blockIdx.x * blockDim.x + threadIdx.x;
    if (i >= E) return;
    if (g_is64) {
        const long long* p = (const long long*)ei;
        g_src[i] = (int)p[i];
        g_dst[i] = (int)p[(size_t)E + i];
    } else {
        const int* p = (const int*)ei;
        g_src[i] = p[i];
        g_dst[i] = p[(size_t)E + i];
    }
}

__global__ void k_init(int n, int F) {
    size_t total = (size_t)n * F;
    size_t stride = (size_t)gridDim.x * blockDim.x;
    for (size_t i = blockIdx.x * (size_t)blockDim.x + threadIdx.x; i < total; i += stride) {
        g_ACC[i] = 0.f;
        if (i < (size_t)n) { g_mkey[i] = 0u; g_s[i] = 0.f; }
        if (i < (size_t)F) { g_cs[i] = 0.f; g_cq[i] = 0.f; }
    }
}

// h = X @ W^T ; alpha_s = h.a_src ; alpha_d = h.a_dst
template<int IN, int OUT>
__global__ void k_gemm(const float* __restrict__ Xin, const float* __restrict__ W,
                       const float* __restrict__ asv, const float* __restrict__ adv, int n) {
    const float* X = Xin ? Xin : g_IN;
    __shared__ float Wt[IN * OUT];     // transposed: Wt[k*OUT + o]
    __shared__ float av[2 * OUT];
    __shared__ float xs[8][IN];
    int tid = threadIdx.x;
    for (int i = tid; i < IN * OUT; i += blockDim.x) {
        int o = i / IN, k = i % IN;
        Wt[k * OUT + o] = W[i];
    }
    for (int i = tid; i < OUT; i += blockDim.x) { av[i] = asv[i]; av[OUT + i] = adv[i]; }
    __syncthreads();
    int warp = tid >> 5, lane = tid & 31;
    constexpr int OP = OUT / 32;       // 2 or 4 outputs per lane
    for (int row = blockIdx.x * 8 + warp; row < n; row += gridDim.x * 8) {
        __syncwarp();
        for (int k = lane; k < IN; k += 32) xs[warp][k] = X[(size_t)row * IN + k];
        __syncwarp();
        float acc[OP];
        #pragma unroll
        for (int p = 0; p < OP; p++) acc[p] = 0.f;
        #pragma unroll 8
        for (int k = 0; k < IN; k++) {
            float xv = xs[warp][k];
            if constexpr (OP == 2) {
                float2 wv = *reinterpret_cast<const float2*>(&Wt[k * OUT + lane * 2]);
                acc[0] += xv * wv.x; acc[1] += xv * wv.y;
            } else {
                float4 wv = *reinterpret_cast<const float4*>(&Wt[k * OUT + lane * 4]);
                acc[0] += xv * wv.x; acc[1] += xv * wv.y;
                acc[2] += xv * wv.z; acc[3] += xv * wv.w;
            }
        }
        float sA = 0.f, sD = 0.f;
        #pragma unroll
        for (int p = 0; p < OP; p++) {
            g_P[(size_t)row * OUT + lane * OP + p] = acc[p];
            sA += acc[p] * av[lane * OP + p];
            sD += acc[p] * av[OUT + lane * OP + p];
        }
        #pragma unroll
        for (int off = 16; off; off >>= 1) {
            sA += __shfl_xor_sync(0xffffffffu, sA, off);
            sD += __shfl_xor_sync(0xffffffffu, sD, off);
        }
        if (lane == 0) { g_as[row] = sA; g_ad[row] = sD; }
    }
}

__global__ void k_edge_max(int E, int n) {
    int i = blockIdx.x * blockDim.x + threadIdx.x;
    int ET = E + n;
    if (i >= ET) return;
    int s, d;
    if (i < E) { s = g_src[i]; d = g_dst[i]; } else { s = d = i - E; }
    float e = g_as[s] + g_ad[d];
    e = e > 0.f ? e : NEG_SLOPE * e;
    g_e[i] = e;
    atomicMax(&g_mkey[d], fenc(e));
}

__global__ void k_edge_exp(int E, int n) {
    int i = blockIdx.x * blockDim.x + threadIdx.x;
    int ET = E + n;
    if (i >= ET) return;
    int d = (i < E) ? g_dst[i] : (i - E);
    float m = fdec(g_mkey[d]);
    float w = __expf(g_e[i] - m);
    g_e[i] = w;
    atomicAdd(&g_s[d], w);
}

// out[dst] += (w / s[dst]) * h[src]   — F/4 lanes per edge, vector red
template<int F>
__global__ void k_edge_agg(int E, int n) {
    constexpr int G = F / 4;
    long long t = (long long)blockIdx.x * blockDim.x + threadIdx.x;
    int edge = (int)(t / G);
    int lg   = (int)(t % G);
    int ET = E + n;
    if (edge >= ET) return;
    int s, d;
    if (edge < E) { s = g_src[edge]; d = g_dst[edge]; } else { s = d = edge - E; }
    float coeff = g_e[edge] / (g_s[d] + 1e-16f);
    float4 v = *reinterpret_cast<const float4*>(&g_P[(size_t)s * F + lg * 4]);
    float a = v.x * coeff, b = v.y * coeff, c = v.z * coeff, w = v.w * coeff;
    float* dp = &g_ACC[(size_t)d * F + lg * 4];
    asm volatile("red.global.add.v4.f32 [%0], {%1,%2,%3,%4};"
                 :: "l"(dp), "f"(a), "f"(b), "f"(c), "f"(w) : "memory");
}

// acc = relu(acc + b); accumulate column stats. blockDim == F.
__global__ void k_post(const float* __restrict__ b, int n, int F) {
    int f = threadIdx.x;
    float bias = b[f];
    float sum = 0.f, sq = 0.f;
    for (int row = blockIdx.x; row < n; row += gridDim.x) {
        float v = g_ACC[(size_t)row * F + f] + bias;
        v = fmaxf(v, 0.f);
        g_ACC[(size_t)row * F + f] = v;
        sum += v; sq += v * v;
    }
    atomicAdd(&g_cs[f], sum);
    atomicAdd(&g_cq[f], sq);
}

__global__ void k_bn(const float* __restrict__ g, const float* __restrict__ be, int n, int F) {
    size_t total = (size_t)n * F;
    size_t i = blockIdx.x * (size_t)blockDim.x + threadIdx.x;
    if (i >= total) return;
    int f = (int)(i % F);
    float inv_n = 1.f / (float)n;
    float mu  = g_cs[f] * inv_n;
    float var = g_cq[f] * inv_n - mu * mu;
    g_IN[i] = g[f] * (g_ACC[i] - mu) * rsqrtf(var + EPS) + be[f];
}

__global__ void k_final(const float* __restrict__ x, const float* __restrict__ b,
                        float* __restrict__ out, int n) {
    size_t total = (size_t)n * 128;
    size_t i = blockIdx.x * (size_t)blockDim.x + threadIdx.x;
    if (i >= total) return;
    int f = (int)(i & 127);
    float xh = fmaxf(g_ACC[i] + b[f], 0.f);
    out[i] = fabsf(x[i] - xh);
    out[total + i] = xh;
}

// ---------------- launch ----------------
extern "C" void kernel_launch(void* const* d_in, const int* in_sizes, int n_in,
                              void* d_out, int out_size) {
    const float* x   = (const float*)d_in[0];
    const void*  ei  = d_in[1];
    const float* W1  = (const float*)d_in[2];
    const float* a1s = (const float*)d_in[3];
    const float* a1d = (const float*)d_in[4];
    const float* b1  = (const float*)d_in[5];
    const float* g1  = (const float*)d_in[6];
    const float* be1 = (const float*)d_in[7];
    const float* W2  = (const float*)d_in[8];
    const float* a2s = (const float*)d_in[9];
    const float* a2d = (const float*)d_in[10];
    const float* b2  = (const float*)d_in[11];
    const float* g2  = (const float*)d_in[12];
    const float* be2 = (const float*)d_in[13];
    const float* W3  = (const float*)d_in[14];
    const float* a3s = (const float*)d_in[15];
    const float* a3d = (const float*)d_in[16];
    const float* b3  = (const float*)d_in[17];
    const float* g3  = (const float*)d_in[18];
    const float* be3 = (const float*)d_in[19];
    const float* W4  = (const float*)d_in[20];
    const float* a4s = (const float*)d_in[21];
    const float* a4d = (const float*)d_in[22];
    const float* b4  = (const float*)d_in[23];
    float* out = (float*)d_out;

    int n = in_sizes[0] / 128;     // 50000
    int E = in_sizes[1] / 2;       // 800000 (element count is 2E for either dtype)
    int ET = E + n;

    const int TB = 256;
    int eb  = (ET + TB - 1) / TB;
    int cb  = (E + TB - 1) / TB;

    k_detect<<<1, 32>>>((const int*)ei);
    k_convert<<<cb, TB>>>(ei, E);

    // ---- layer 1: 128 -> 64, BN ----
    k_init<<<4096, TB>>>(n, 64);
    k_gemm<128, 64><<<592, 256>>>(x, W1, a1s, a1d, n);
    k_edge_max<<<eb, TB>>>(E, n);
    k_edge_exp<<<eb, TB>>>(E, n);
    {
        long long th = (long long)ET * 16;
        k_edge_agg<64><<<(int)((th + TB - 1) / TB), TB>>>(E, n);
    }
    k_post<<<1184, 64>>>(b1, n, 64);
    k_bn<<<(int)(((size_t)n * 64 + TB - 1) / TB), TB>>>(g1, be1, n, 64);

    // ---- layer 2: 64 -> 64, BN ----
    k_init<<<4096, TB>>>(n, 64);
    k_gemm<64, 64><<<592, 256>>>(nullptr, W2, a2s, a2d, n);
    k_edge_max<<<eb, TB>>>(E, n);
    k_edge_exp<<<eb, TB>>>(E, n);
    {
        long long th = (long long)ET * 16;
        k_edge_agg<64><<<(int)((th + TB - 1) / TB), TB>>>(E, n);
    }
    k_post<<<1184, 64>>>(b2, n, 64);
    k_bn<<<(int)(((size_t)n * 64 + TB - 1) / TB), TB>>>(g2, be2, n, 64);

    // ---- layer 3: 64 -> 64, BN ----
    k_init<<<4096, TB>>>(n, 64);
    k_gemm<64, 64><<<592, 256>>>(nullptr, W3, a3s, a3d, n);
    k_edge_max<<<eb, TB>>>(E, n);
    k_edge_exp<<<eb, TB>>>(E, n);
    {
        long long th = (long long)ET * 16;
        k_edge_agg<64><<<(int)((th + TB - 1) / TB), TB>>>(E, n);
    }
    k_post<<<1184, 64>>>(b3, n, 64);
    k_bn<<<(int)(((size_t)n * 64 + TB - 1) / TB), TB>>>(g3, be3, n, 64);

    // ---- layer 4: 64 -> 128, no BN; final output ----
    k_init<<<4096, TB>>>(n, 128);
    k_gemm<64, 128><<<592, 256>>>(nullptr, W4, a4s, a4d, n);
    k_edge_max<<<eb, TB>>>(E, n);
    k_edge_exp<<<eb, TB>>>(E, n);
    {
        long long th = (long long)ET * 32;
        k_edge_agg<128><<<(int)((th + TB - 1) / TB), TB>>>(E, n);
    }
    k_final<<<(int)(((size_t)n * 128 + TB - 1) / TB), TB>>>(x, b4, out, n);
}

// round 4
// speedup vs baseline: 1.1530x; 1.1530x over previous
#include <cuda_runtime.h>
#include <cuda_bf16.h>
#include <math.h>

#define MAXN 50000
#define MAXE 800000
#define EPS 1e-5f
#define NEG_SLOPE 0.2f

// ---------------- scratch (device globals; no allocation allowed) ----------------
__device__ __align__(16) float g_P  [(size_t)MAXN * 128];   // h = x @ W^T
__device__ __align__(16) float g_ACC[(size_t)MAXN * 128];   // aggregation accumulator
__device__ float    g_as [MAXN];
__device__ float    g_ad [MAXN];
__device__ float    g_s  [MAXN];                 // softmax denominator (sum of exp)
__device__ int      g_src[MAXE];
__device__ int      g_dst[MAXE];
__device__ float    g_cs [128];                  // column sums (BN)
__device__ float    g_cq [128];                  // column sumsq (BN)
__device__ int      g_is64;                      // edge_index dtype flag

// ---------------- kernels ----------------

// Detect whether edge_index is int64 or int32 (odd 32-bit words all zero => int64).
__global__ void k_detect(const int* __restrict__ w) {
    if (threadIdx.x == 0 && blockIdx.x == 0) {
        int all_zero = 1;
        for (int i = 0; i < 64; i++)
            if (w[2 * i + 1] != 0) { all_zero = 0; break; }
        g_is64 = all_zero;
    }
}

__global__ void k_convert(const void* __restrict__ ei, int E) {
    int i = blockIdx.x * blockDim.x + threadIdx.x;
    if (i >= E) return;
    if (g_is64) {
        const long long* p = (const long long*)ei;
        g_src[i] = (int)p[i];
        g_dst[i] = (int)p[(size_t)E + i];
    } else {
        const int* p = (const int*)ei;
        g_src[i] = p[i];
        g_dst[i] = p[(size_t)E + i];
    }
}

__global__ void k_init(int n, int F) {
    size_t total = (size_t)n * F;
    size_t stride = (size_t)gridDim.x * blockDim.x;
    for (size_t i = blockIdx.x * (size_t)blockDim.x + threadIdx.x; i < total; i += stride) {
        g_ACC[i] = 0.f;
        if (i < (size_t)n) g_s[i] = 0.f;
        if (i < (size_t)128) { g_cs[i] = 0.f; g_cq[i] = 0.f; }
    }
}

// h = bn(X) @ W^T ; alpha_s = h.a_src ; alpha_d = h.a_dst
// 256 threads, 8 warps x 4 rows = 32 rows per block. Register-tiled.
// Xin == nullptr => read g_ACC (device symbol resolved in device code).
template<int IN, int OUT, bool BN>
__global__ void __launch_bounds__(256) k_gemm(
        const float* __restrict__ Xin, const float* __restrict__ W,
        const float* __restrict__ asv, const float* __restrict__ adv,
        const float* __restrict__ gam, const float* __restrict__ bet, int n) {
    const float* X = Xin ? Xin : g_ACC;
    __shared__ float Wt[IN * OUT];      // transposed: Wt[k*OUT + o]
    __shared__ float xs[32 * IN];
    int tid = threadIdx.x;

    for (int i = tid; i < IN * OUT; i += 256) {
        int o = i / IN, k = i % IN;
        Wt[k * OUT + o] = W[i];
    }

    int row0 = blockIdx.x * 32;
    int nr = min(32, n - row0);
    const float4* Xv = (const float4*)(X + (size_t)row0 * IN);
    int tot4 = (nr * IN) >> 2;

    if constexpr (BN) {
        __shared__ float cs[IN], csh[IN];
        float inv_n = 1.f / (float)n;
        for (int i = tid; i < IN; i += 256) {
            float mu  = g_cs[i] * inv_n;
            float var = g_cq[i] * inv_n - mu * mu;
            float sc  = gam[i] * rsqrtf(var + EPS);
            cs[i]  = sc;
            csh[i] = bet[i] - mu * sc;
        }
        __syncthreads();
        for (int i = tid; i < tot4; i += 256) {
            float4 v = Xv[i];
            int c = (i * 4) & (IN - 1);
            v.x = fmaf(v.x, cs[c + 0], csh[c + 0]);
            v.y = fmaf(v.y, cs[c + 1], csh[c + 1]);
            v.z = fmaf(v.z, cs[c + 2], csh[c + 2]);
            v.w = fmaf(v.w, cs[c + 3], csh[c + 3]);
            ((float4*)xs)[i] = v;
        }
    } else {
        for (int i = tid; i < tot4; i += 256) ((float4*)xs)[i] = Xv[i];
    }
    __syncthreads();

    int warp = tid >> 5, lane = tid & 31;
    constexpr int OP = OUT / 32;        // 2 (OUT=64) or 4 (OUT=128)
    float acc[4][OP];
    #pragma unroll
    for (int r = 0; r < 4; r++)
        #pragma unroll
        for (int p = 0; p < OP; p++) acc[r][p] = 0.f;

    const float* xb = &xs[(warp * 4) * IN];
    #pragma unroll 4
    for (int k4 = 0; k4 < IN / 4; k4++) {
        float4 xv[4];
        #pragma unroll
        for (int r = 0; r < 4; r++)
            xv[r] = *(const float4*)&xb[r * IN + k4 * 4];
        #pragma unroll
        for (int kk = 0; kk < 4; kk++) {
            float wv[OP];
            if constexpr (OP == 2) {
                float2 t = *(const float2*)&Wt[(k4 * 4 + kk) * OUT + lane * 2];
                wv[0] = t.x; wv[1] = t.y;
            } else {
                float4 t = *(const float4*)&Wt[(k4 * 4 + kk) * OUT + lane * 4];
                wv[0] = t.x; wv[1] = t.y; wv[2] = t.z; wv[3] = t.w;
            }
            #pragma unroll
            for (int r = 0; r < 4; r++) {
                const float* xf = (const float*)&xv[r];
                float xvk = xf[kk];
                #pragma unroll
                for (int p = 0; p < OP; p++) acc[r][p] += xvk * wv[p];
            }
        }
    }

    float avs[OP], avd[OP];
    #pragma unroll
    for (int p = 0; p < OP; p++) {
        avs[p] = asv[lane * OP + p];
        avd[p] = adv[lane * OP + p];
    }

    #pragma unroll
    for (int r = 0; r < 4; r++) {
        int row = row0 + warp * 4 + r;
        if (row >= n) break;
        if constexpr (OP == 2) {
            *(float2*)&g_P[(size_t)row * OUT + lane * 2] = make_float2(acc[r][0], acc[r][1]);
        } else {
            *(float4*)&g_P[(size_t)row * OUT + lane * 4] =
                make_float4(acc[r][0], acc[r][1], acc[r][2], acc[r][3]);
        }
        float sA = 0.f, sD = 0.f;
        #pragma unroll
        for (int p = 0; p < OP; p++) { sA += acc[r][p] * avs[p]; sD += acc[r][p] * avd[p]; }
        #pragma unroll
        for (int off = 16; off; off >>= 1) {
            sA += __shfl_xor_sync(0xffffffffu, sA, off);
            sD += __shfl_xor_sync(0xffffffffu, sD, off);
        }
        if (lane == 0) { g_as[row] = sA; g_ad[row] = sD; }
    }
}

// ONE fused edge pass: w = exp(leaky(as[s]+ad[d])); s[d] += w; ACC[d] += w*h[s]
// F/4 lanes per edge. Normalization deferred to k_post/k_final (linear).
template<int F>
__global__ void __launch_bounds__(256) k_edge(int E, int n) {
    constexpr int G = F / 4;            // 16 or 32
    constexpr int LG2 = (F == 64) ? 4 : 5;
    unsigned t = blockIdx.x * 256u + threadIdx.x;
    unsigned edge = t >> LG2;
    unsigned lg = t & (G - 1);
    if (edge >= (unsigned)(E + n)) return;
    int s, d;
    if (edge < (unsigned)E) { s = g_src[edge]; d = g_dst[edge]; }
    else { s = d = edge - E; }
    float e = g_as[s] + g_ad[d];
    e = e > 0.f ? e : NEG_SLOPE * e;
    float w = __expf(e);
    if (lg == 0) atomicAdd(&g_s[d], w);
    float4 v = *(const float4*)&g_P[(size_t)s * F + lg * 4];
    float a = v.x * w, b = v.y * w, c = v.z * w, dd = v.w * w;
    float* dp = &g_ACC[(size_t)d * F + lg * 4];
    asm volatile("red.global.add.v4.f32 [%0], {%1,%2,%3,%4};"
                 :: "l"(dp), "f"(a), "f"(b), "f"(c), "f"(dd) : "memory");
}

// acc = relu(acc/s + b); accumulate column stats. blockDim == F.
__global__ void k_post(const float* __restrict__ b, int n, int F) {
    int f = threadIdx.x;
    float bias = b[f];
    float sum = 0.f, sq = 0.f;
    for (int row = blockIdx.x; row < n; row += gridDim.x) {
        float inv = 1.f / (g_s[row] + 1e-16f);
        float v = fmaf(g_ACC[(size_t)row * F + f], inv, bias);
        v = fmaxf(v, 0.f);
        g_ACC[(size_t)row * F + f] = v;
        sum += v; sq += v * v;
    }
    atomicAdd(&g_cs[f], sum);
    atomicAdd(&g_cq[f], sq);
}

__global__ void k_final(const float* __restrict__ x, const float* __restrict__ b,
                        float* __restrict__ out, int n) {
    size_t total = (size_t)n * 128;
    size_t i = blockIdx.x * (size_t)blockDim.x + threadIdx.x;
    if (i >= total) return;
    int f = (int)(i & 127);
    int row = (int)(i >> 7);
    float inv = 1.f / (g_s[row] + 1e-16f);
    float xh = fmaxf(fmaf(g_ACC[i], inv, b[f]), 0.f);
    out[i] = fabsf(x[i] - xh);
    out[total + i] = xh;
}

// ---------------- launch ----------------
extern "C" void kernel_launch(void* const* d_in, const int* in_sizes, int n_in,
                              void* d_out, int out_size) {
    const float* x   = (const float*)d_in[0];
    const void*  ei  = d_in[1];
    const float* W1  = (const float*)d_in[2];
    const float* a1s = (const float*)d_in[3];
    const float* a1d = (const float*)d_in[4];
    const float* b1  = (const float*)d_in[5];
    const float* g1  = (const float*)d_in[6];
    const float* be1 = (const float*)d_in[7];
    const float* W2  = (const float*)d_in[8];
    const float* a2s = (const float*)d_in[9];
    const float* a2d = (const float*)d_in[10];
    const float* b2  = (const float*)d_in[11];
    const float* g2  = (const float*)d_in[12];
    const float* be2 = (const float*)d_in[13];
    const float* W3  = (const float*)d_in[14];
    const float* a3s = (const float*)d_in[15];
    const float* a3d = (const float*)d_in[16];
    const float* b3  = (const float*)d_in[17];
    const float* g3  = (const float*)d_in[18];
    const float* be3 = (const float*)d_in[19];
    const float* W4  = (const float*)d_in[20];
    const float* a4s = (const float*)d_in[21];
    const float* a4d = (const float*)d_in[22];
    const float* b4  = (const float*)d_in[23];
    float* out = (float*)d_out;

    int n = in_sizes[0] / 128;     // 50000
    int E = in_sizes[1] / 2;       // 800000
    int ET = E + n;

    const int TB = 256;
    int cb = (E + TB - 1) / TB;
    int gb = (n + 31) / 32;
    int eb64  = (int)(((long long)ET * 16 + TB - 1) / TB);
    int eb128 = (int)(((long long)ET * 32 + TB - 1) / TB);

    k_detect<<<1, 32>>>((const int*)ei);
    k_convert<<<cb, TB>>>(ei, E);

    // ---- layer 1: 128 -> 64 ----
    k_gemm<128, 64, false><<<gb, 256>>>(x, W1, a1s, a1d, nullptr, nullptr, n);
    k_init<<<2048, TB>>>(n, 64);
    k_edge<64><<<eb64, TB>>>(E, n);
    k_post<<<1184, 64>>>(b1, n, 64);

    // ---- layer 2: 64 -> 64 (BN of layer1 fused into load; X = g_ACC via device symbol) ----
    k_gemm<64, 64, true><<<gb, 256>>>(nullptr, W2, a2s, a2d, g1, be1, n);
    k_init<<<2048, TB>>>(n, 64);
    k_edge<64><<<eb64, TB>>>(E, n);
    k_post<<<1184, 64>>>(b2, n, 64);

    // ---- layer 3: 64 -> 64 ----
    k_gemm<64, 64, true><<<gb, 256>>>(nullptr, W3, a3s, a3d, g2, be2, n);
    k_init<<<2048, TB>>>(n, 64);
    k_edge<64><<<eb64, TB>>>(E, n);
    k_post<<<1184, 64>>>(b3, n, 64);

    // ---- layer 4: 64 -> 128 ----
    k_gemm<64, 128, true><<<gb, 256>>>(nullptr, W4, a4s, a4d, g3, be3, n);
    k_init<<<2048, TB>>>(n, 128);
    k_edge<128><<<eb128, TB>>>(E, n);
    k_final<<<(int)(((size_t)n * 128 + TB - 1) / TB), TB>>>(x, b4, out, n);
}

// round 7
// speedup vs baseline: 1.5382x; 1.3340x over previous
#include <cuda_runtime.h>
#include <cuda_bf16.h>
#include <math.h>

#define MAXN 50000
#define MAXE 800000
#define EPS 1e-5f
#define NEG_SLOPE 0.2f

// ---------------- scratch (device globals; no allocation allowed) ----------------
__device__ __align__(16) float g_P  [(size_t)MAXN * 128];   // h = x @ W^T
__device__ __align__(16) float g_ACC[(size_t)MAXN * 128];   // node features (layer output)
__device__ float    g_as [MAXN];
__device__ float    g_ad [MAXN];
__device__ int      g_src[MAXE];
__device__ int      g_dst[MAXE];
__device__ int      g_cnt[MAXN + 1];             // histogram -> CSR rowptr
__device__ int      g_pos[MAXN];                 // scatter cursor
__device__ int      g_esrc[MAXE + MAXN];         // src ids sorted by dst (self-loop first)
__device__ float    g_st_s[3][128];              // per-layer BN column sums
__device__ float    g_st_q[3][128];              // per-layer BN column sumsq
__device__ int      g_is64;                      // edge_index dtype flag

// ---------------- setup kernels ----------------

__global__ void k_detect(const int* __restrict__ w) {
    if (threadIdx.x == 0 && blockIdx.x == 0) {
        int all_zero = 1;
        for (int i = 0; i < 64; i++)
            if (w[2 * i + 1] != 0) { all_zero = 0; break; }
        g_is64 = all_zero;
    }
}

__global__ void k_zero(int n) {
    int i = blockIdx.x * blockDim.x + threadIdx.x;
    if (i <= n) g_cnt[i] = 0;
    if (i < 3 * 128) { ((float*)g_st_s)[i] = 0.f; ((float*)g_st_q)[i] = 0.f; }
}

// convert edge dtype + histogram dst
__global__ void k_setup(const void* __restrict__ ei, int E) {
    int i = blockIdx.x * blockDim.x + threadIdx.x;
    if (i >= E) return;
    int s, d;
    if (g_is64) {
        const long long* p = (const long long*)ei;
        s = (int)p[i]; d = (int)p[(size_t)E + i];
    } else {
        const int* p = (const int*)ei;
        s = p[i]; d = p[(size_t)E + i];
    }
    g_src[i] = s; g_dst[i] = d;
    atomicAdd(&g_cnt[d], 1);
}

// single-block exclusive scan of (count+1) -> rowptr; place self-loop at slot 0
__global__ void __launch_bounds__(1024) k_scan(int n) {
    __shared__ int partial[1024];
    int tid = threadIdx.x;
    int chunk = (n + 1023) / 1024;
    int beg = tid * chunk, end = min(beg + chunk, n);
    int sum = 0;
    for (int i = beg; i < end; i++) sum += g_cnt[i] + 1;   // +1 self-loop
    partial[tid] = sum;
    __syncthreads();
    for (int off = 1; off < 1024; off <<= 1) {
        int v = (tid >= off) ? partial[tid - off] : 0;
        __syncthreads();
        partial[tid] += v;
        __syncthreads();
    }
    int run = tid ? partial[tid - 1] : 0;
    for (int i = beg; i < end; i++) {
        int c = g_cnt[i] + 1;
        g_cnt[i] = run;          // rowptr
        g_esrc[run] = i;         // self-loop in first slot
        g_pos[i] = run + 1;
        run += c;
    }
    if (tid == 1023) g_cnt[n] = partial[1023];
}

__global__ void k_scatter(int E) {
    int i = blockIdx.x * blockDim.x + threadIdx.x;
    if (i >= E) return;
    int pos = atomicAdd(&g_pos[g_dst[i]], 1);
    g_esrc[pos] = g_src[i];
}

// ---------------- GEMM: h = bn(X) @ W^T ; alpha_s/alpha_d ----------------
// 256 threads, 8 warps x 4 rows = 32 rows per block. Register-tiled.
template<int IN, int OUT, bool BN>
__global__ void __launch_bounds__(256) k_gemm(
        const float* __restrict__ Xin, const float* __restrict__ W,
        const float* __restrict__ asv, const float* __restrict__ adv,
        const float* __restrict__ gam, const float* __restrict__ bet,
        int slot, int n) {
    const float* X = Xin ? Xin : g_ACC;
    __shared__ float Wt[IN * OUT];
    __shared__ float xs[32 * IN];
    int tid = threadIdx.x;

    for (int i = tid; i < IN * OUT; i += 256) {
        int o = i / IN, k = i % IN;
        Wt[k * OUT + o] = W[i];
    }

    int row0 = blockIdx.x * 32;
    int nr = min(32, n - row0);
    const float4* Xv = (const float4*)(X + (size_t)row0 * IN);
    int tot4 = (nr * IN) >> 2;

    if constexpr (BN) {
        __shared__ float cs[IN], csh[IN];
        float inv_n = 1.f / (float)n;
        for (int i = tid; i < IN; i += 256) {
            float mu  = g_st_s[slot][i] * inv_n;
            float var = g_st_q[slot][i] * inv_n - mu * mu;
            float sc  = gam[i] * rsqrtf(var + EPS);
            cs[i]  = sc;
            csh[i] = bet[i] - mu * sc;
        }
        __syncthreads();
        for (int i = tid; i < tot4; i += 256) {
            float4 v = Xv[i];
            int c = (i * 4) & (IN - 1);
            v.x = fmaf(v.x, cs[c + 0], csh[c + 0]);
            v.y = fmaf(v.y, cs[c + 1], csh[c + 1]);
            v.z = fmaf(v.z, cs[c + 2], csh[c + 2]);
            v.w = fmaf(v.w, cs[c + 3], csh[c + 3]);
            ((float4*)xs)[i] = v;
        }
    } else {
        for (int i = tid; i < tot4; i += 256) ((float4*)xs)[i] = Xv[i];
    }
    __syncthreads();

    int warp = tid >> 5, lane = tid & 31;
    constexpr int OP = OUT / 32;
    float acc[4][OP];
    #pragma unroll
    for (int r = 0; r < 4; r++)
        #pragma unroll
        for (int p = 0; p < OP; p++) acc[r][p] = 0.f;

    const float* xb = &xs[(warp * 4) * IN];
    #pragma unroll 4
    for (int k4 = 0; k4 < IN / 4; k4++) {
        float4 xv[4];
        #pragma unroll
        for (int r = 0; r < 4; r++)
            xv[r] = *(const float4*)&xb[r * IN + k4 * 4];
        #pragma unroll
        for (int kk = 0; kk < 4; kk++) {
            float wv[OP];
            if constexpr (OP == 2) {
                float2 t = *(const float2*)&Wt[(k4 * 4 + kk) * OUT + lane * 2];
                wv[0] = t.x; wv[1] = t.y;
            } else {
                float4 t = *(const float4*)&Wt[(k4 * 4 + kk) * OUT + lane * 4];
                wv[0] = t.x; wv[1] = t.y; wv[2] = t.z; wv[3] = t.w;
            }
            #pragma unroll
            for (int r = 0; r < 4; r++) {
                const float* xf = (const float*)&xv[r];
                float xvk = xf[kk];
                #pragma unroll
                for (int p = 0; p < OP; p++) acc[r][p] += xvk * wv[p];
            }
        }
    }

    float avs[OP], avd[OP];
    #pragma unroll
    for (int p = 0; p < OP; p++) {
        avs[p] = asv[lane * OP + p];
        avd[p] = adv[lane * OP + p];
    }

    #pragma unroll
    for (int r = 0; r < 4; r++) {
        int row = row0 + warp * 4 + r;
        if (row >= n) break;
        if constexpr (OP == 2) {
            *(float2*)&g_P[(size_t)row * OUT + lane * 2] = make_float2(acc[r][0], acc[r][1]);
        } else {
            *(float4*)&g_P[(size_t)row * OUT + lane * 4] =
                make_float4(acc[r][0], acc[r][1], acc[r][2], acc[r][3]);
        }
        float sA = 0.f, sD = 0.f;
        #pragma unroll
        for (int p = 0; p < OP; p++) { sA += acc[r][p] * avs[p]; sD += acc[r][p] * avd[p]; }
        #pragma unroll
        for (int off = 16; off; off >>= 1) {
            sA += __shfl_xor_sync(0xffffffffu, sA, off);
            sD += __shfl_xor_sync(0xffffffffu, sD, off);
        }
        if (lane == 0) { g_as[row] = sA; g_ad[row] = sD; }
    }
}

// ---------------- CSR edge pass: atomic-free aggregation ----------------
// One G=F/4 lane group per dst node. Accumulate sum(w*h[src]), sum(w) in regs,
// normalize, bias+relu; FINAL writes |x-xh| and xh, else writes ACC + BN stats.
template<int F, bool FINAL>
__global__ void __launch_bounds__(256) k_edge(
        const float* __restrict__ bias, const float* __restrict__ x,
        float* __restrict__ out, int slot, int n) {
    constexpr int G = F / 4;            // 16 or 32
    constexpr int LG2 = (F == 64) ? 4 : 5;

    __shared__ float s_sum[F], s_sq[F];
    int tid = threadIdx.x;
    if constexpr (!FINAL) {
        if (tid < F) { s_sum[tid] = 0.f; s_sq[tid] = 0.f; }
        __syncthreads();
    }

    int node = (blockIdx.x * 256 + tid) >> LG2;
    int lg = tid & (G - 1);
    bool active = node < n;

    float ax = 0.f, ay = 0.f, az = 0.f, aw = 0.f, wsum = 0.f, inv = 0.f;
    if (active) {
        int beg = g_cnt[node], end = g_cnt[node + 1];
        float ad = g_ad[node];
        int e = beg;
        for (; e + 1 < end; e += 2) {
            int s0 = g_esrc[e], s1 = g_esrc[e + 1];
            float a0 = g_as[s0], a1 = g_as[s1];
            float4 v0 = *(const float4*)&g_P[(size_t)s0 * F + lg * 4];
            float4 v1 = *(const float4*)&g_P[(size_t)s1 * F + lg * 4];
            float e0 = a0 + ad; e0 = e0 > 0.f ? e0 : NEG_SLOPE * e0;
            float e1 = a1 + ad; e1 = e1 > 0.f ? e1 : NEG_SLOPE * e1;
            float w0 = __expf(e0), w1 = __expf(e1);
            wsum += w0 + w1;
            ax = fmaf(w0, v0.x, fmaf(w1, v1.x, ax));
            ay = fmaf(w0, v0.y, fmaf(w1, v1.y, ay));
            az = fmaf(w0, v0.z, fmaf(w1, v1.z, az));
            aw = fmaf(w0, v0.w, fmaf(w1, v1.w, aw));
        }
        if (e < end) {
            int s0 = g_esrc[e];
            float a0 = g_as[s0];
            float4 v0 = *(const float4*)&g_P[(size_t)s0 * F + lg * 4];
            float e0 = a0 + ad; e0 = e0 > 0.f ? e0 : NEG_SLOPE * e0;
            float w0 = __expf(e0);
            wsum += w0;
            ax = fmaf(w0, v0.x, ax); ay = fmaf(w0, v0.y, ay);
            az = fmaf(w0, v0.z, az); aw = fmaf(w0, v0.w, aw);
        }
        inv = 1.f / (wsum + 1e-16f);
    }

    if constexpr (FINAL) {
        if (active) {
            float4 bv = *(const float4*)&bias[lg * 4];
            float4 xh;
            xh.x = fmaxf(fmaf(ax, inv, bv.x), 0.f);
            xh.y = fmaxf(fmaf(ay, inv, bv.y), 0.f);
            xh.z = fmaxf(fmaf(az, inv, bv.z), 0.f);
            xh.w = fmaxf(fmaf(aw, inv, bv.w), 0.f);
            size_t o = (size_t)node * F + lg * 4;
            float4 xv = *(const float4*)&x[o];
            float4 df;
            df.x = fabsf(xv.x - xh.x); df.y = fabsf(xv.y - xh.y);
            df.z = fabsf(xv.z - xh.z); df.w = fabsf(xv.w - xh.w);
            *(float4*)&out[o] = df;
            *(float4*)&out[(size_t)n * F + o] = xh;
        }
    } else {
        float4 v = {0.f, 0.f, 0.f, 0.f};
        if (active) {
            float4 bv = *(const float4*)&bias[lg * 4];
            v.x = fmaxf(fmaf(ax, inv, bv.x), 0.f);
            v.y = fmaxf(fmaf(ay, inv, bv.y), 0.f);
            v.z = fmaxf(fmaf(az, inv, bv.z), 0.f);
            v.w = fmaxf(fmaf(aw, inv, bv.w), 0.f);
            *(float4*)&g_ACC[(size_t)node * F + lg * 4] = v;
        }
        // pair-reduce across the two 16-lane halves of each warp, then smem atomics
        float p0 = v.x + __shfl_down_sync(0xffffffffu, v.x, 16);
        float p1 = v.y + __shfl_down_sync(0xffffffffu, v.y, 16);
        float p2 = v.z + __shfl_down_sync(0xffffffffu, v.z, 16);
        float p3 = v.w + __shfl_down_sync(0xffffffffu, v.w, 16);
        float q0 = v.x * v.x + __shfl_down_sync(0xffffffffu, v.x * v.x, 16);
        float q1 = v.y * v.y + __shfl_down_sync(0xffffffffu, v.y * v.y, 16);
        float q2 = v.z * v.z + __shfl_down_sync(0xffffffffu, v.z * v.z, 16);
        float q3 = v.w * v.w + __shfl_down_sync(0xffffffffu, v.w * v.w, 16);
        if ((tid & 31) < 16) {
            int f = lg * 4;
            atomicAdd(&s_sum[f + 0], p0); atomicAdd(&s_sum[f + 1], p1);
            atomicAdd(&s_sum[f + 2], p2); atomicAdd(&s_sum[f + 3], p3);
            atomicAdd(&s_sq[f + 0], q0);  atomicAdd(&s_sq[f + 1], q1);
            atomicAdd(&s_sq[f + 2], q2);  atomicAdd(&s_sq[f + 3], q3);
        }
        __syncthreads();
        if (tid < F) {
            atomicAdd(&g_st_s[slot][tid], s_sum[tid]);
            atomicAdd(&g_st_q[slot][tid], s_sq[tid]);
        }
    }
}

// ---------------- launch ----------------
extern "C" void kernel_launch(void* const* d_in, const int* in_sizes, int n_in,
                              void* d_out, int out_size) {
    const float* x   = (const float*)d_in[0];
    const void*  ei  = d_in[1];
    const float* W1  = (const float*)d_in[2];
    const float* a1s = (const float*)d_in[3];
    const float* a1d = (const float*)d_in[4];
    const float* b1  = (const float*)d_in[5];
    const float* g1  = (const float*)d_in[6];
    const float* be1 = (const float*)d_in[7];
    const float* W2  = (const float*)d_in[8];
    const float* a2s = (const float*)d_in[9];
    const float* a2d = (const float*)d_in[10];
    const float* b2  = (const float*)d_in[11];
    const float* g2  = (const float*)d_in[12];
    const float* be2 = (const float*)d_in[13];
    const float* W3  = (const float*)d_in[14];
    const float* a3s = (const float*)d_in[15];
    const float* a3d = (const float*)d_in[16];
    const float* b3  = (const float*)d_in[17];
    const float* g3  = (const float*)d_in[18];
    const float* be3 = (const float*)d_in[19];
    const float* W4  = (const float*)d_in[20];
    const float* a4s = (const float*)d_in[21];
    const float* a4d = (const float*)d_in[22];
    const float* b4  = (const float*)d_in[23];
    float* out = (float*)d_out;

    int n = in_sizes[0] / 128;     // 50000
    int E = in_sizes[1] / 2;       // 800000

    const int TB = 256;
    int cb = (E + TB - 1) / TB;
    int gb = (n + 31) / 32;
    int zb = (n + 1 + TB - 1) / TB;
    int e64  = (n * 16 + TB - 1) / TB;   // 16 lanes per node
    int e128 = (n * 32 + TB - 1) / TB;   // 32 lanes per node

    // CSR build (once per launch)
    k_detect<<<1, 32>>>((const int*)ei);
    k_zero<<<zb, TB>>>(n);
    k_setup<<<cb, TB>>>(ei, E);
    k_scan<<<1, 1024>>>(n);
    k_scatter<<<cb, TB>>>(E);

    // ---- layer 1: 128 -> 64 ----
    k_gemm<128, 64, false><<<gb, 256>>>(x, W1, a1s, a1d, nullptr, nullptr, 0, n);
    k_edge<64, false><<<e64, TB>>>(b1, nullptr, nullptr, 0, n);

    // ---- layer 2: 64 -> 64 (BN of layer1 fused, stats slot 0) ----
    k_gemm<64, 64, true><<<gb, 256>>>(nullptr, W2, a2s, a2d, g1, be1, 0, n);
    k_edge<64, false><<<e64, TB>>>(b2, nullptr, nullptr, 1, n);

    // ---- layer 3: 64 -> 64 ----
    k_gemm<64, 64, true><<<gb, 256>>>(nullptr, W3, a3s, a3d, g2, be2, 1, n);
    k_edge<64, false><<<e64, TB>>>(b3, nullptr, nullptr, 2, n);

    // ---- layer 4: 64 -> 128, fused final output ----
    k_gemm<64, 128, true><<<gb, 256>>>(nullptr, W4, a4s, a4d, g3, be3, 2, n);
    k_edge<128, true><<<e128, TB>>>(b4, x, out, 0, n);
}

// round 9
// speedup vs baseline: 1.8473x; 1.2010x over previous
#include <cuda_runtime.h>
#include <cuda_bf16.h>
#include <math.h>

#define MAXN 50000
#define MAXE 800000
#define EPS 1e-5f
#define NEG_SLOPE 0.2f

#define PS_THREADS 8192            // scan partition: 32 blocks x 256 threads
#define PS_PER_T   8               // pass-B serial factor (8192/1024)

// ---------------- scratch (device globals; no allocation allowed) ----------------
__device__ __align__(16) float g_P  [(size_t)MAXN * 128];   // h = x @ W^T
__device__ __align__(16) float g_ACC[(size_t)MAXN * 128];   // node features (layer output)
__device__ float    g_as [MAXN];
__device__ float    g_ad [MAXN];
__device__ int      g_src[MAXE];
__device__ int      g_dst[MAXE];
__device__ int      g_cnt[MAXN + 1];             // histogram -> CSR rowptr
__device__ int      g_pos[MAXN];                 // scatter cursor
__device__ int      g_esrc[MAXE + MAXN];         // src ids sorted by dst (self-loop first)
__device__ int      g_tsum[PS_THREADS];          // per-thread chunk sums / prefixes
__device__ float    g_st_s[3][128];              // per-layer BN column sums
__device__ float    g_st_q[3][128];              // per-layer BN column sumsq
__device__ int      g_is64;                      // edge_index dtype flag

// ---------------- setup kernels ----------------

__global__ void k_detect(const int* __restrict__ w) {
    if (threadIdx.x == 0 && blockIdx.x == 0) {
        int all_zero = 1;
        for (int i = 0; i < 64; i++)
            if (w[2 * i + 1] != 0) { all_zero = 0; break; }
        g_is64 = all_zero;
    }
}

__global__ void k_zero(int n) {
    int i = blockIdx.x * blockDim.x + threadIdx.x;
    if (i <= n) g_cnt[i] = 0;
    if (i < 3 * 128) { ((float*)g_st_s)[i] = 0.f; ((float*)g_st_q)[i] = 0.f; }
}

// convert edge dtype + histogram dst
__global__ void k_setup(const void* __restrict__ ei, int E) {
    int i = blockIdx.x * blockDim.x + threadIdx.x;
    if (i >= E) return;
    int s, d;
    if (g_is64) {
        const long long* p = (const long long*)ei;
        s = (int)p[i]; d = (int)p[(size_t)E + i];
    } else {
        const int* p = (const int*)ei;
        s = p[i]; d = p[(size_t)E + i];
    }
    g_src[i] = s; g_dst[i] = d;
    atomicAdd(&g_cnt[d], 1);
}

// ---- parallel CSR scan: A) per-thread chunk sums ----
__global__ void k_psum(int n) {
    int t = blockIdx.x * blockDim.x + threadIdx.x;   // 0..PS_THREADS-1
    int chunk = (n + PS_THREADS - 1) / PS_THREADS;
    int beg = t * chunk, end = min(beg + chunk, n);
    int sum = 0;
    for (int i = beg; i < end; i++) sum += g_cnt[i] + 1;   // +1 self-loop
    g_tsum[t] = sum;
}

// ---- B) exclusive scan of the 8192 chunk sums (1 block, 1024 threads) ----
__global__ void __launch_bounds__(1024) k_scant(int n) {
    __shared__ int partial[1024];
    int tid = threadIdx.x;
    int vals[PS_PER_T];
    int base = tid * PS_PER_T;
    int s = 0;
    #pragma unroll
    for (int j = 0; j < PS_PER_T; j++) { vals[j] = g_tsum[base + j]; s += vals[j]; }
    partial[tid] = s;
    __syncthreads();
    for (int off = 1; off < 1024; off <<= 1) {
        int v = (tid >= off) ? partial[tid - off] : 0;
        __syncthreads();
        partial[tid] += v;
        __syncthreads();
    }
    int run = tid ? partial[tid - 1] : 0;
    #pragma unroll
    for (int j = 0; j < PS_PER_T; j++) { g_tsum[base + j] = run; run += vals[j]; }
    if (tid == 1023) g_cnt[n] = partial[1023];
}

// ---- C) fill rowptr, self-loop slot, scatter cursor ----
__global__ void k_fill(int n) {
    int t = blockIdx.x * blockDim.x + threadIdx.x;
    int chunk = (n + PS_THREADS - 1) / PS_THREADS;
    int beg = t * chunk, end = min(beg + chunk, n);
    int run = g_tsum[t];
    for (int i = beg; i < end; i++) {
        int c = g_cnt[i] + 1;
        g_cnt[i] = run;          // rowptr
        g_esrc[run] = i;         // self-loop in first slot
        g_pos[i] = run + 1;
        run += c;
    }
}

__global__ void k_scatter(int E) {
    int i = blockIdx.x * blockDim.x + threadIdx.x;
    if (i >= E) return;
    int pos = atomicAdd(&g_pos[g_dst[i]], 1);
    g_esrc[pos] = g_src[i];
}

// ---------------- GEMM: h = bn(X) @ W^T ; alpha_s/alpha_d ----------------
// 256 threads, 8 warps x 4 rows = 32 rows per block. Register-tiled.
template<int IN, int OUT, bool BN>
__global__ void __launch_bounds__(256) k_gemm(
        const float* __restrict__ Xin, const float* __restrict__ W,
        const float* __restrict__ asv, const float* __restrict__ adv,
        const float* __restrict__ gam, const float* __restrict__ bet,
        int slot, int n) {
    const float* X = Xin ? Xin : g_ACC;
    __shared__ float Wt[IN * OUT];
    __shared__ float xs[32 * IN];
    int tid = threadIdx.x;

    for (int i = tid; i < IN * OUT; i += 256) {
        int o = i / IN, k = i % IN;
        Wt[k * OUT + o] = W[i];
    }

    int row0 = blockIdx.x * 32;
    int nr = min(32, n - row0);
    const float4* Xv = (const float4*)(X + (size_t)row0 * IN);
    int tot4 = (nr * IN) >> 2;

    if constexpr (BN) {
        __shared__ float cs[IN], csh[IN];
        float inv_n = 1.f / (float)n;
        for (int i = tid; i < IN; i += 256) {
            float mu  = g_st_s[slot][i] * inv_n;
            float var = g_st_q[slot][i] * inv_n - mu * mu;
            float sc  = gam[i] * rsqrtf(var + EPS);
            cs[i]  = sc;
            csh[i] = bet[i] - mu * sc;
        }
        __syncthreads();
        for (int i = tid; i < tot4; i += 256) {
            float4 v = Xv[i];
            int c = (i * 4) & (IN - 1);
            v.x = fmaf(v.x, cs[c + 0], csh[c + 0]);
            v.y = fmaf(v.y, cs[c + 1], csh[c + 1]);
            v.z = fmaf(v.z, cs[c + 2], csh[c + 2]);
            v.w = fmaf(v.w, cs[c + 3], csh[c + 3]);
            ((float4*)xs)[i] = v;
        }
    } else {
        for (int i = tid; i < tot4; i += 256) ((float4*)xs)[i] = Xv[i];
    }
    __syncthreads();

    int warp = tid >> 5, lane = tid & 31;
    constexpr int OP = OUT / 32;
    float acc[4][OP];
    #pragma unroll
    for (int r = 0; r < 4; r++)
        #pragma unroll
        for (int p = 0; p < OP; p++) acc[r][p] = 0.f;

    const float* xb = &xs[(warp * 4) * IN];
    #pragma unroll 4
    for (int k4 = 0; k4 < IN / 4; k4++) {
        float4 xv[4];
        #pragma unroll
        for (int r = 0; r < 4; r++)
            xv[r] = *(const float4*)&xb[r * IN + k4 * 4];
        #pragma unroll
        for (int kk = 0; kk < 4; kk++) {
            float wv[OP];
            if constexpr (OP == 2) {
                float2 t = *(const float2*)&Wt[(k4 * 4 + kk) * OUT + lane * 2];
                wv[0] = t.x; wv[1] = t.y;
            } else {
                float4 t = *(const float4*)&Wt[(k4 * 4 + kk) * OUT + lane * 4];
                wv[0] = t.x; wv[1] = t.y; wv[2] = t.z; wv[3] = t.w;
            }
            #pragma unroll
            for (int r = 0; r < 4; r++) {
                const float* xf = (const float*)&xv[r];
                float xvk = xf[kk];
                #pragma unroll
                for (int p = 0; p < OP; p++) acc[r][p] += xvk * wv[p];
            }
        }
    }

    float avs[OP], avd[OP];
    #pragma unroll
    for (int p = 0; p < OP; p++) {
        avs[p] = asv[lane * OP + p];
        avd[p] = adv[lane * OP + p];
    }

    #pragma unroll
    for (int r = 0; r < 4; r++) {
        int row = row0 + warp * 4 + r;
        if (row >= n) break;
        if constexpr (OP == 2) {
            *(float2*)&g_P[(size_t)row * OUT + lane * 2] = make_float2(acc[r][0], acc[r][1]);
        } else {
            *(float4*)&g_P[(size_t)row * OUT + lane * 4] =
                make_float4(acc[r][0], acc[r][1], acc[r][2], acc[r][3]);
        }
        float sA = 0.f, sD = 0.f;
        #pragma unroll
        for (int p = 0; p < OP; p++) { sA += acc[r][p] * avs[p]; sD += acc[r][p] * avd[p]; }
        #pragma unroll
        for (int off = 16; off; off >>= 1) {
            sA += __shfl_xor_sync(0xffffffffu, sA, off);
            sD += __shfl_xor_sync(0xffffffffu, sD, off);
        }
        if (lane == 0) { g_as[row] = sA; g_ad[row] = sD; }
    }
}

// ---------------- CSR edge pass: atomic-free aggregation ----------------
// One G=F/4 lane group per dst node. Accumulate sum(w*h[src]), sum(w) in regs,
// normalize, bias+relu; FINAL writes |x-xh| and xh, else writes ACC + BN stats.
template<int F, bool FINAL>
__global__ void __launch_bounds__(256) k_edge(
        const float* __restrict__ bias, const float* __restrict__ x,
        float* __restrict__ out, int slot, int n) {
    constexpr int G = F / 4;            // 16 or 32
    constexpr int LG2 = (F == 64) ? 4 : 5;

    __shared__ float s_sum[F], s_sq[F];
    int tid = threadIdx.x;
    if constexpr (!FINAL) {
        if (tid < F) { s_sum[tid] = 0.f; s_sq[tid] = 0.f; }
        __syncthreads();
    }

    int node = (blockIdx.x * 256 + tid) >> LG2;
    int lg = tid & (G - 1);
    bool active = node < n;

    float ax = 0.f, ay = 0.f, az = 0.f, aw = 0.f, wsum = 0.f, inv = 0.f;
    if (active) {
        int beg = g_cnt[node], end = g_cnt[node + 1];
        float ad = g_ad[node];
        int e = beg;
        for (; e + 1 < end; e += 2) {
            int s0 = g_esrc[e], s1 = g_esrc[e + 1];
            float a0 = g_as[s0], a1 = g_as[s1];
            float4 v0 = *(const float4*)&g_P[(size_t)s0 * F + lg * 4];
            float4 v1 = *(const float4*)&g_P[(size_t)s1 * F + lg * 4];
            float e0 = a0 + ad; e0 = e0 > 0.f ? e0 : NEG_SLOPE * e0;
            float e1 = a1 + ad; e1 = e1 > 0.f ? e1 : NEG_SLOPE * e1;
            float w0 = __expf(e0), w1 = __expf(e1);
            wsum += w0 + w1;
            ax = fmaf(w0, v0.x, fmaf(w1, v1.x, ax));
            ay = fmaf(w0, v0.y, fmaf(w1, v1.y, ay));
            az = fmaf(w0, v0.z, fmaf(w1, v1.z, az));
            aw = fmaf(w0, v0.w, fmaf(w1, v1.w, aw));
        }
        if (e < end) {
            int s0 = g_esrc[e];
            float a0 = g_as[s0];
            float4 v0 = *(const float4*)&g_P[(size_t)s0 * F + lg * 4];
            float e0 = a0 + ad; e0 = e0 > 0.f ? e0 : NEG_SLOPE * e0;
            float w0 = __expf(e0);
            wsum += w0;
            ax = fmaf(w0, v0.x, ax); ay = fmaf(w0, v0.y, ay);
            az = fmaf(w0, v0.z, az); aw = fmaf(w0, v0.w, aw);
        }
        inv = 1.f / (wsum + 1e-16f);
    }

    if constexpr (FINAL) {
        if (active) {
            float4 bv = *(const float4*)&bias[lg * 4];
            float4 xh;
            xh.x = fmaxf(fmaf(ax, inv, bv.x), 0.f);
            xh.y = fmaxf(fmaf(ay, inv, bv.y), 0.f);
            xh.z = fmaxf(fmaf(az, inv, bv.z), 0.f);
            xh.w = fmaxf(fmaf(aw, inv, bv.w), 0.f);
            size_t o = (size_t)node * F + lg * 4;
            float4 xv = *(const float4*)&x[o];
            float4 df;
            df.x = fabsf(xv.x - xh.x); df.y = fabsf(xv.y - xh.y);
            df.z = fabsf(xv.z - xh.z); df.w = fabsf(xv.w - xh.w);
            *(float4*)&out[o] = df;
            *(float4*)&out[(size_t)n * F + o] = xh;
        }
    } else {
        float4 v = {0.f, 0.f, 0.f, 0.f};
        if (active) {
            float4 bv = *(const float4*)&bias[lg * 4];
            v.x = fmaxf(fmaf(ax, inv, bv.x), 0.f);
            v.y = fmaxf(fmaf(ay, inv, bv.y), 0.f);
            v.z = fmaxf(fmaf(az, inv, bv.z), 0.f);
            v.w = fmaxf(fmaf(aw, inv, bv.w), 0.f);
            *(float4*)&g_ACC[(size_t)node * F + lg * 4] = v;
        }
        // pair-reduce across the two 16-lane halves of each warp, then smem atomics
        float p0 = v.x + __shfl_down_sync(0xffffffffu, v.x, 16);
        float p1 = v.y + __shfl_down_sync(0xffffffffu, v.y, 16);
        float p2 = v.z + __shfl_down_sync(0xffffffffu, v.z, 16);
        float p3 = v.w + __shfl_down_sync(0xffffffffu, v.w, 16);
        float q0 = v.x * v.x + __shfl_down_sync(0xffffffffu, v.x * v.x, 16);
        float q1 = v.y * v.y + __shfl_down_sync(0xffffffffu, v.y * v.y, 16);
        float q2 = v.z * v.z + __shfl_down_sync(0xffffffffu, v.z * v.z, 16);
        float q3 = v.w * v.w + __shfl_down_sync(0xffffffffu, v.w * v.w, 16);
        if ((tid & 31) < 16) {
            int f = lg * 4;
            atomicAdd(&s_sum[f + 0], p0); atomicAdd(&s_sum[f + 1], p1);
            atomicAdd(&s_sum[f + 2], p2); atomicAdd(&s_sum[f + 3], p3);
            atomicAdd(&s_sq[f + 0], q0);  atomicAdd(&s_sq[f + 1], q1);
            atomicAdd(&s_sq[f + 2], q2);  atomicAdd(&s_sq[f + 3], q3);
        }
        __syncthreads();
        if (tid < F) {
            atomicAdd(&g_st_s[slot][tid], s_sum[tid]);
            atomicAdd(&g_st_q[slot][tid], s_sq[tid]);
        }
    }
}

// ---------------- launch ----------------
extern "C" void kernel_launch(void* const* d_in, const int* in_sizes, int n_in,
                              void* d_out, int out_size) {
    const float* x   = (const float*)d_in[0];
    const void*  ei  = d_in[1];
    const float* W1  = (const float*)d_in[2];
    const float* a1s = (const float*)d_in[3];
    const float* a1d = (const float*)d_in[4];
    const float* b1  = (const float*)d_in[5];
    const float* g1  = (const float*)d_in[6];
    const float* be1 = (const float*)d_in[7];
    const float* W2  = (const float*)d_in[8];
    const float* a2s = (const float*)d_in[9];
    const float* a2d = (const float*)d_in[10];
    const float* b2  = (const float*)d_in[11];
    const float* g2  = (const float*)d_in[12];
    const float* be2 = (const float*)d_in[13];
    const float* W3  = (const float*)d_in[14];
    const float* a3s = (const float*)d_in[15];
    const float* a3d = (const float*)d_in[16];
    const float* b3  = (const float*)d_in[17];
    const float* g3  = (const float*)d_in[18];
    const float* be3 = (const float*)d_in[19];
    const float* W4  = (const float*)d_in[20];
    const float* a4s = (const float*)d_in[21];
    const float* a4d = (const float*)d_in[22];
    const float* b4  = (const float*)d_in[23];
    float* out = (float*)d_out;

    int n = in_sizes[0] / 128;     // 50000
    int E = in_sizes[1] / 2;       // 800000

    const int TB = 256;
    int cb = (E + TB - 1) / TB;
    int gb = (n + 31) / 32;
    int zb = (n + 1 + TB - 1) / TB;
    int e64  = (n * 16 + TB - 1) / TB;   // 16 lanes per node
    int e128 = (n * 32 + TB - 1) / TB;   // 32 lanes per node

    // CSR build (once per launch) — parallel scan
    k_detect<<<1, 32>>>((const int*)ei);
    k_zero<<<zb, TB>>>(n);
    k_setup<<<cb, TB>>>(ei, E);
    k_psum<<<PS_THREADS / TB, TB>>>(n);
    k_scant<<<1, 1024>>>(n);
    k_fill<<<PS_THREADS / TB, TB>>>(n);
    k_scatter<<<cb, TB>>>(E);

    // ---- layer 1: 128 -> 64 ----
    k_gemm<128, 64, false><<<gb, 256>>>(x, W1, a1s, a1d, nullptr, nullptr, 0, n);
    k_edge<64, false><<<e64, TB>>>(b1, nullptr, nullptr, 0, n);

    // ---- layer 2: 64 -> 64 (BN of layer1 fused, stats slot 0) ----
    k_gemm<64, 64, true><<<gb, 256>>>(nullptr, W2, a2s, a2d, g1, be1, 0, n);
    k_edge<64, false><<<e64, TB>>>(b2, nullptr, nullptr, 1, n);

    // ---- layer 3: 64 -> 64 ----
    k_gemm<64, 64, true><<<gb, 256>>>(nullptr, W3, a3s, a3d, g2, be2, 1, n);
    k_edge<64, false><<<e64, TB>>>(b3, nullptr, nullptr, 2, n);

    // ---- layer 4: 64 -> 128, fused final output ----
    k_gemm<64, 128, true><<<gb, 256>>>(nullptr, W4, a4s, a4d, g3, be3, 2, n);
    k_edge<128, true><<<e128, TB>>>(b4, x, out, 0, n);
}